// round 10
// baseline (speedup 1.0000x reference)
#include <cuda_runtime.h>

// Problem constants (fixed by the dataset)
#define PB   2      // batch
#define PN   2048   // atoms
#define PM   64     // neighbors
#define PF   128    // features
#define PH1  64
#define PH2  64

#define NW   4      // warps per MLP block
#define APW  4      // atoms per warp
#define APB  (NW * APW)   // atoms per block = 16

// Padded weight row strides (conflict-free banks without index math)
#define W0S  129    // (129*l + f) % 32 == (l+f)%32 -> distinct per lane
#define W1S  65

// Scratch (allocation-free rule: __device__ globals)
__device__ float g_grad[PB * PN * PF];   // dEi/dx per atom, 4 MB (L2-resident)
__device__ float g_Ei[PB * PN];          // per-atom energies

// ---------------------------------------------------------------------------
// Kernel 1: warp-private MLP fwd + analytic input-gradient bwd.
// Processes atoms [atom_base, atom_base + gridDim.x*APB). Unchanged math.
// ---------------------------------------------------------------------------
__global__ void __launch_bounds__(NW * 32) mlp_kernel(
    const float* __restrict__ image,
    const float* __restrict__ W0,     // [H1, F]
    const float* __restrict__ W1,     // [H2, H1]
    const float* __restrict__ Wout,   // [1, H2]
    int atom_base)
{
    extern __shared__ float dyn[];
    float* sW0  = dyn;                     // 64*129 floats, padded rows
    float* sW1  = sW0 + PH1 * W0S;         // 64*65 floats, padded rows
    float* sX   = sW1 + PH2 * W1S;         // NW*APW*PF, plain [at][f]
    float* sBuf = sX + NW * APW * PF;      // NW*APW*PH1, plain [at][j]
    float* sWo  = sBuf + NW * APW * PH1;   // 64

    const int tid = threadIdx.x;
    const int w   = tid >> 5;
    const int l   = tid & 31;

    // ---- stage weights (padded) ----
    for (int i = tid; i < PH1 * PF; i += NW * 32)
        sW0[(i >> 7) * W0S + (i & 127)] = W0[i];
    for (int i = tid; i < PH2 * PH1; i += NW * 32)
        sW1[(i >> 6) * W1S + (i & 63)] = W1[i];
    if (tid < PH2) sWo[tid] = Wout[tid];
    __syncthreads();

    const int a0 = atom_base + blockIdx.x * APB + w * APW;
    float* wX = sX + w * (APW * PF);
    float* wB = sBuf + w * (APW * PH1);

    // ---- stage x for APW atoms: contiguous float4, conflict-free ----
    {
        const float4* src = (const float4*)(image + (size_t)a0 * PF);
        float4* dst = (float4*)wX;
        #pragma unroll
        for (int it = 0; it < APW; it++) dst[it * 32 + l] = src[it * 32 + l];
    }
    __syncwarp();

    const float* w0a = sW0 + l * W0S;          // row l
    const float* w0b = sW0 + (l + 32) * W0S;   // row l+32
    const float* w1a = sW1 + l * W1S;
    const float* w1b = sW1 + (l + 32) * W1S;

    // ---- L0 forward: h0[j] = sigmoid(sum_f W0[j,f] x[f]), j = l, l+32 ----
    float h0v[2][APW];
    {
        float acc[2][APW];
        #pragma unroll
        for (int h = 0; h < 2; h++)
            #pragma unroll
            for (int at = 0; at < APW; at++) acc[h][at] = 0.f;

        #pragma unroll 4
        for (int f = 0; f < PF; f += 4) {
            float4 xv[APW];
            #pragma unroll
            for (int at = 0; at < APW; at++)
                xv[at] = *(const float4*)(wX + at * PF + f);
            #pragma unroll
            for (int ff = 0; ff < 4; ff++) {
                const float wa = w0a[f + ff];
                const float wb = w0b[f + ff];
                #pragma unroll
                for (int at = 0; at < APW; at++) {
                    const float xe = ((const float*)&xv[at])[ff];
                    acc[0][at] += wa * xe;
                    acc[1][at] += wb * xe;
                }
            }
        }
        #pragma unroll
        for (int h = 0; h < 2; h++)
            #pragma unroll
            for (int at = 0; at < APW; at++)
                h0v[h][at] = 1.f / (1.f + __expf(-acc[h][at]));
    }
    #pragma unroll
    for (int at = 0; at < APW; at++) {
        wB[at * PH1 + l]      = h0v[0][at];
        wB[at * PH1 + l + 32] = h0v[1][at];
    }
    __syncwarp();

    // ---- L1 forward: h1[k] = sigmoid(sum_j W1[k,j] h0[j]), k = l, l+32 ----
    float h1v[2][APW];
    {
        float acc[2][APW];
        #pragma unroll
        for (int h = 0; h < 2; h++)
            #pragma unroll
            for (int at = 0; at < APW; at++) acc[h][at] = 0.f;

        #pragma unroll 4
        for (int j = 0; j < PH1; j += 4) {
            float4 hv[APW];
            #pragma unroll
            for (int at = 0; at < APW; at++)
                hv[at] = *(const float4*)(wB + at * PH1 + j);
            #pragma unroll
            for (int ff = 0; ff < 4; ff++) {
                const float wa = w1a[j + ff];
                const float wb = w1b[j + ff];
                #pragma unroll
                for (int at = 0; at < APW; at++) {
                    const float he = ((const float*)&hv[at])[ff];
                    acc[0][at] += wa * he;
                    acc[1][at] += wb * he;
                }
            }
        }
        #pragma unroll
        for (int h = 0; h < 2; h++)
            #pragma unroll
            for (int at = 0; at < APW; at++)
                h1v[h][at] = 1.f / (1.f + __expf(-acc[h][at]));
    }

    // ---- Ei = sum_k h1[k]*Wout[k] (deterministic warp shuffle reduce) ----
    const float wo0 = sWo[l], wo1 = sWo[l + 32];
    #pragma unroll
    for (int at = 0; at < APW; at++) {
        float v = h1v[0][at] * wo0 + h1v[1][at] * wo1;
        #pragma unroll
        for (int o = 16; o; o >>= 1) v += __shfl_down_sync(0xffffffffu, v, o);
        if (l == 0) g_Ei[a0 + at] = v;
    }
    __syncwarp();   // everyone done reading h0 from wB

    // ---- t1 = h1*(1-h1)*Wout -> publish (overwrites h0 buffer) ----
    #pragma unroll
    for (int at = 0; at < APW; at++) {
        wB[at * PH1 + l]      = h1v[0][at] * (1.f - h1v[0][at]) * wo0;
        wB[at * PH1 + l + 32] = h1v[1][at] * (1.f - h1v[1][at]) * wo1;
    }
    __syncwarp();

    // ---- gH1[j] = sum_k t1[k]*W1[k,j]; t0 = h0*(1-h0)*gH1, j = l, l+32 ----
    float t0v[2][APW];
    {
        float acc[2][APW];
        #pragma unroll
        for (int h = 0; h < 2; h++)
            #pragma unroll
            for (int at = 0; at < APW; at++) acc[h][at] = 0.f;

        #pragma unroll 4
        for (int k = 0; k < PH2; k += 4) {
            float4 tv[APW];
            #pragma unroll
            for (int at = 0; at < APW; at++)
                tv[at] = *(const float4*)(wB + at * PH1 + k);
            #pragma unroll
            for (int kk = 0; kk < 4; kk++) {
                // column read of padded W1: banks (k*65 + l) % 32 distinct
                const float wa = sW1[(k + kk) * W1S + l];
                const float wb = sW1[(k + kk) * W1S + l + 32];
                #pragma unroll
                for (int at = 0; at < APW; at++) {
                    const float te = ((const float*)&tv[at])[kk];
                    acc[0][at] += wa * te;
                    acc[1][at] += wb * te;
                }
            }
        }
        #pragma unroll
        for (int h = 0; h < 2; h++)
            #pragma unroll
            for (int at = 0; at < APW; at++)
                t0v[h][at] = h0v[h][at] * (1.f - h0v[h][at]) * acc[h][at];
    }
    __syncwarp();   // done reading t1

    // ---- publish t0 ----
    #pragma unroll
    for (int at = 0; at < APW; at++) {
        wB[at * PH1 + l]      = t0v[0][at];
        wB[at * PH1 + l + 32] = t0v[1][at];
    }
    __syncwarp();

    // ---- g[f] = sum_j t0[j]*W0[j,f], f = l + 32q ----
    {
        float acc[4][APW];
        #pragma unroll
        for (int q = 0; q < 4; q++)
            #pragma unroll
            for (int at = 0; at < APW; at++) acc[q][at] = 0.f;

        for (int j = 0; j < PH1; j += 4) {
            float4 tv[APW];
            #pragma unroll
            for (int at = 0; at < APW; at++)
                tv[at] = *(const float4*)(wB + at * PH1 + j);
            #pragma unroll
            for (int jj = 0; jj < 4; jj++) {
                const float* wrow = sW0 + (j + jj) * W0S + l;
                #pragma unroll
                for (int q = 0; q < 4; q++) {
                    const float wv = wrow[32 * q];   // banks (j + l) % 32 distinct
                    #pragma unroll
                    for (int at = 0; at < APW; at++)
                        acc[q][at] += wv * ((const float*)&tv[at])[jj];
                }
            }
        }
        #pragma unroll
        for (int at = 0; at < APW; at++)
            #pragma unroll
            for (int q = 0; q < 4; q++)
                g_grad[(size_t)(a0 + at) * PF + l + 32 * q] = acc[q][at];
    }
}

// ---------------------------------------------------------------------------
// Kernel 2: deterministic Etot reduction (no float atomics)
// ---------------------------------------------------------------------------
__global__ void etot_kernel(float* __restrict__ out)
{
    const int b = blockIdx.x;
    const int tid = threadIdx.x;
    __shared__ float sm[256];
    float s = 0.f;
    for (int i = tid; i < PN; i += 256) s += g_Ei[b * PN + i];
    sm[tid] = s;
    __syncthreads();
    #pragma unroll
    for (int o = 128; o; o >>= 1) {
        if (tid < o) sm[tid] += sm[tid + o];
        __syncthreads();
    }
    if (tid == 0) out[b] = sm[0];
}

// ---------------------------------------------------------------------------
// Kernel 3: force via double-buffered smem pipeline (per-batch slice).
// ---------------------------------------------------------------------------
__global__ void __launch_bounds__(128) force_kernel(
    const float* __restrict__ dfeat,
    const int*   __restrict__ neighbor,
    float*       __restrict__ out,     // out[0..1]=Etot, force at out+2
    int bn_base)
{
    const int bn  = bn_base + blockIdx.x;  // 0 .. B*N-1
    const int b   = bn >> 11;              // / PN
    const int tid = threadIdx.x;

    __shared__ float4 buf4[2][768];    // 2 x 12 KB dfeat chunks (8 rows x 384 f)
    __shared__ float4 gs4[2][256];     // 2 x 4 KB g chunks (8 rows x 128 f)
    __shared__ int    sidx[PM];
    __shared__ float  sred[4][3];

    if (tid < PM) sidx[tid] = neighbor[bn * PM + tid];
    __syncthreads();

    const float4* df4 = (const float4*)(dfeat + (size_t)bn * (PM * PF * 3));
    const float4* g4  = (const float4*)(g_grad + (size_t)b * PN * PF);

    float4 rd[6], rg[2];

    // ---- prologue: chunk 0 ----
    #pragma unroll
    for (int k = 0; k < 6; k++) rd[k] = df4[k * 128 + tid];
    #pragma unroll
    for (int k = 0; k < 2; k++) {
        const int q = k * 128 + tid;
        const int ml = q >> 5, c2 = q & 31;    // warp-uniform row, lane = col
        const int nv = sidx[ml];
        rg[k] = (nv > 0) ? g4[(size_t)(nv - 1) * 32 + c2]
                         : make_float4(0.f, 0.f, 0.f, 0.f);
    }
    #pragma unroll
    for (int k = 0; k < 6; k++) buf4[0][k * 128 + tid] = rd[k];
    #pragma unroll
    for (int k = 0; k < 2; k++) gs4[0][k * 128 + tid] = rg[k];
    __syncthreads();

    float ax = 0.f, ay = 0.f, az = 0.f;

    #pragma unroll
    for (int c = 0; c < 8; c++) {
        const int cur = c & 1;
        if (c < 7) {   // prefetch chunk c+1 into registers
            #pragma unroll
            for (int k = 0; k < 6; k++)
                rd[k] = df4[(c + 1) * 768 + k * 128 + tid];
            #pragma unroll
            for (int k = 0; k < 2; k++) {
                const int q = k * 128 + tid;
                const int ml = q >> 5, c2 = q & 31;
                const int nv = sidx[(c + 1) * 8 + ml];
                rg[k] = (nv > 0) ? g4[(size_t)(nv - 1) * 32 + c2]
                                 : make_float4(0.f, 0.f, 0.f, 0.f);
            }
        }

        // consume chunk c: uniform indexing, no divergence
        const float* bb = (const float*)buf4[cur];
        const float* gg = (const float*)gs4[cur];
        #pragma unroll
        for (int mm = 0; mm < 8; mm++) {
            const float gv = gg[mm * 128 + tid];          // banks tid%32
            const float* row = bb + mm * 384 + tid * 3;   // banks (3*tid)%32
            ax += gv * row[0];
            ay += gv * row[1];
            az += gv * row[2];
        }

        if (c < 7) {   // stage prefetched chunk into the other buffer
            #pragma unroll
            for (int k = 0; k < 6; k++) buf4[cur ^ 1][k * 128 + tid] = rd[k];
            #pragma unroll
            for (int k = 0; k < 2; k++) gs4[cur ^ 1][k * 128 + tid] = rg[k];
        }
        __syncthreads();
    }

    // reduce 128 threads -> 3 floats
    #pragma unroll
    for (int o = 16; o; o >>= 1) {
        ax += __shfl_down_sync(0xffffffffu, ax, o);
        ay += __shfl_down_sync(0xffffffffu, ay, o);
        az += __shfl_down_sync(0xffffffffu, az, o);
    }
    const int w = tid >> 5, l = tid & 31;
    if (l == 0) { sred[w][0] = ax; sred[w][1] = ay; sred[w][2] = az; }
    __syncthreads();
    if (tid < 3) {
        const float v = sred[0][tid] + sred[1][tid] + sred[2][tid] + sred[3][tid];
        out[2 + bn * 3 + tid] = v * 1e10f;
    }
}

// ---------------------------------------------------------------------------
// Launch: batch-pipelined. Dependency is per-batch (force(b) needs only
// g_grad of batch b), so force(b0) overlaps mlp(b1) via a captured side
// stream. Stream/events created once on the first (non-capture) call; the
// launched work is identical on every call.
// ---------------------------------------------------------------------------
extern "C" void kernel_launch(void* const* d_in, const int* in_sizes, int n_in,
                              void* d_out, int out_size)
{
    const float* image    = (const float*)d_in[0];
    const float* dfeat    = (const float*)d_in[1];
    const int*   neighbor = (const int*)  d_in[2];
    // d_in[3] Egroup_weight, d_in[4] divider: unused by the reference math
    const float* W0       = (const float*)d_in[5];
    const float* W1       = (const float*)d_in[6];
    const float* Wout     = (const float*)d_in[7];
    float* out = (float*)d_out;

    static cudaStream_t side = nullptr;
    static cudaEvent_t  evM0 = nullptr, evJ = nullptr;
    if (side == nullptr) {
        cudaStreamCreateWithFlags(&side, cudaStreamNonBlocking);
        cudaEventCreateWithFlags(&evM0, cudaEventDisableTiming);
        cudaEventCreateWithFlags(&evJ,  cudaEventDisableTiming);
    }

    const int smem_bytes = (PH1 * W0S + PH2 * W1S + NW * APW * PF
                            + NW * APW * PH1 + PH2) * 4;
    cudaFuncSetAttribute(mlp_kernel, cudaFuncAttributeMaxDynamicSharedMemorySize, smem_bytes);

    const int mlp_blocks_per_batch = PN / APB;   // 128

    // main stream: mlp(b0)
    mlp_kernel<<<mlp_blocks_per_batch, NW * 32, smem_bytes>>>(image, W0, W1, Wout, 0);
    cudaEventRecord(evM0, 0);

    // side stream (forked after mlp0): mlp(b1) -> etot -> force(b1)
    cudaStreamWaitEvent(side, evM0, 0);
    mlp_kernel<<<mlp_blocks_per_batch, NW * 32, smem_bytes, side>>>(image, W0, W1, Wout, PN);
    etot_kernel<<<PB, 256, 0, side>>>(out);
    force_kernel<<<PN, 128, 0, side>>>(dfeat, neighbor, out, PN);
    cudaEventRecord(evJ, side);

    // main stream: force(b0) concurrent with side-stream mlp(b1)/force(b1)
    force_kernel<<<PN, 128>>>(dfeat, neighbor, out, 0);
    cudaStreamWaitEvent(0, evJ, 0);
}

// round 11
// speedup vs baseline: 1.0967x; 1.0967x over previous
#include <cuda_runtime.h>

// Problem constants (fixed by the dataset)
#define PB   2      // batch
#define PN   2048   // atoms
#define PM   64     // neighbors
#define PF   128    // features
#define PH1  64
#define PH2  64

#define NW   4      // warps per MLP block
#define APW  4      // atoms per warp
#define APB  (NW * APW)   // atoms per block = 16

// Padded weight row strides (conflict-free banks without index math)
#define W0S  129    // (129*l + f) % 32 == (l+f)%32 -> distinct per lane
#define W1S  65

// Scratch (allocation-free rule: __device__ globals)
__device__ float g_grad[PB * PN * PF];   // dEi/dx per atom, 4 MB (L2-resident)
__device__ float g_Ei[PB * PN];          // per-atom energies

// cp.async helpers (16-byte, cache-global)
__device__ __forceinline__ void cp_async16(void* smem_dst, const void* gmem_src) {
    unsigned s = (unsigned)__cvta_generic_to_shared(smem_dst);
    asm volatile("cp.async.cg.shared.global [%0], [%1], 16;" :: "r"(s), "l"(gmem_src));
}
#define CP_COMMIT() asm volatile("cp.async.commit_group;")
#define CP_WAIT0()  asm volatile("cp.async.wait_group 0;")

// ---------------------------------------------------------------------------
// Kernel 1: warp-private MLP fwd + analytic input-gradient bwd. (round-7 best)
// ---------------------------------------------------------------------------
__global__ void __launch_bounds__(NW * 32) mlp_kernel(
    const float* __restrict__ image,
    const float* __restrict__ W0,     // [H1, F]
    const float* __restrict__ W1,     // [H2, H1]
    const float* __restrict__ Wout)   // [1, H2]
{
    extern __shared__ float dyn[];
    float* sW0  = dyn;                     // 64*129 floats, padded rows
    float* sW1  = sW0 + PH1 * W0S;         // 64*65 floats, padded rows
    float* sX   = sW1 + PH2 * W1S;         // NW*APW*PF, plain [at][f]
    float* sBuf = sX + NW * APW * PF;      // NW*APW*PH1, plain [at][j]
    float* sWo  = sBuf + NW * APW * PH1;   // 64

    const int tid = threadIdx.x;
    const int w   = tid >> 5;
    const int l   = tid & 31;

    for (int i = tid; i < PH1 * PF; i += NW * 32)
        sW0[(i >> 7) * W0S + (i & 127)] = W0[i];
    for (int i = tid; i < PH2 * PH1; i += NW * 32)
        sW1[(i >> 6) * W1S + (i & 63)] = W1[i];
    if (tid < PH2) sWo[tid] = Wout[tid];
    __syncthreads();

    const int a0 = blockIdx.x * APB + w * APW;
    float* wX = sX + w * (APW * PF);
    float* wB = sBuf + w * (APW * PH1);

    {
        const float4* src = (const float4*)(image + (size_t)a0 * PF);
        float4* dst = (float4*)wX;
        #pragma unroll
        for (int it = 0; it < APW; it++) dst[it * 32 + l] = src[it * 32 + l];
    }
    __syncwarp();

    const float* w0a = sW0 + l * W0S;
    const float* w0b = sW0 + (l + 32) * W0S;
    const float* w1a = sW1 + l * W1S;
    const float* w1b = sW1 + (l + 32) * W1S;

    // ---- L0 forward ----
    float h0v[2][APW];
    {
        float acc[2][APW];
        #pragma unroll
        for (int h = 0; h < 2; h++)
            #pragma unroll
            for (int at = 0; at < APW; at++) acc[h][at] = 0.f;

        #pragma unroll 4
        for (int f = 0; f < PF; f += 4) {
            float4 xv[APW];
            #pragma unroll
            for (int at = 0; at < APW; at++)
                xv[at] = *(const float4*)(wX + at * PF + f);
            #pragma unroll
            for (int ff = 0; ff < 4; ff++) {
                const float wa = w0a[f + ff];
                const float wb = w0b[f + ff];
                #pragma unroll
                for (int at = 0; at < APW; at++) {
                    const float xe = ((const float*)&xv[at])[ff];
                    acc[0][at] += wa * xe;
                    acc[1][at] += wb * xe;
                }
            }
        }
        #pragma unroll
        for (int h = 0; h < 2; h++)
            #pragma unroll
            for (int at = 0; at < APW; at++)
                h0v[h][at] = 1.f / (1.f + __expf(-acc[h][at]));
    }
    #pragma unroll
    for (int at = 0; at < APW; at++) {
        wB[at * PH1 + l]      = h0v[0][at];
        wB[at * PH1 + l + 32] = h0v[1][at];
    }
    __syncwarp();

    // ---- L1 forward ----
    float h1v[2][APW];
    {
        float acc[2][APW];
        #pragma unroll
        for (int h = 0; h < 2; h++)
            #pragma unroll
            for (int at = 0; at < APW; at++) acc[h][at] = 0.f;

        #pragma unroll 4
        for (int j = 0; j < PH1; j += 4) {
            float4 hv[APW];
            #pragma unroll
            for (int at = 0; at < APW; at++)
                hv[at] = *(const float4*)(wB + at * PH1 + j);
            #pragma unroll
            for (int ff = 0; ff < 4; ff++) {
                const float wa = w1a[j + ff];
                const float wb = w1b[j + ff];
                #pragma unroll
                for (int at = 0; at < APW; at++) {
                    const float he = ((const float*)&hv[at])[ff];
                    acc[0][at] += wa * he;
                    acc[1][at] += wb * he;
                }
            }
        }
        #pragma unroll
        for (int h = 0; h < 2; h++)
            #pragma unroll
            for (int at = 0; at < APW; at++)
                h1v[h][at] = 1.f / (1.f + __expf(-acc[h][at]));
    }

    // ---- Ei ----
    const float wo0 = sWo[l], wo1 = sWo[l + 32];
    #pragma unroll
    for (int at = 0; at < APW; at++) {
        float v = h1v[0][at] * wo0 + h1v[1][at] * wo1;
        #pragma unroll
        for (int o = 16; o; o >>= 1) v += __shfl_down_sync(0xffffffffu, v, o);
        if (l == 0) g_Ei[a0 + at] = v;
    }
    __syncwarp();

    // ---- t1 ----
    #pragma unroll
    for (int at = 0; at < APW; at++) {
        wB[at * PH1 + l]      = h1v[0][at] * (1.f - h1v[0][at]) * wo0;
        wB[at * PH1 + l + 32] = h1v[1][at] * (1.f - h1v[1][at]) * wo1;
    }
    __syncwarp();

    // ---- gH1 -> t0 ----
    float t0v[2][APW];
    {
        float acc[2][APW];
        #pragma unroll
        for (int h = 0; h < 2; h++)
            #pragma unroll
            for (int at = 0; at < APW; at++) acc[h][at] = 0.f;

        #pragma unroll 4
        for (int k = 0; k < PH2; k += 4) {
            float4 tv[APW];
            #pragma unroll
            for (int at = 0; at < APW; at++)
                tv[at] = *(const float4*)(wB + at * PH1 + k);
            #pragma unroll
            for (int kk = 0; kk < 4; kk++) {
                const float wa = sW1[(k + kk) * W1S + l];
                const float wb = sW1[(k + kk) * W1S + l + 32];
                #pragma unroll
                for (int at = 0; at < APW; at++) {
                    const float te = ((const float*)&tv[at])[kk];
                    acc[0][at] += wa * te;
                    acc[1][at] += wb * te;
                }
            }
        }
        #pragma unroll
        for (int h = 0; h < 2; h++)
            #pragma unroll
            for (int at = 0; at < APW; at++)
                t0v[h][at] = h0v[h][at] * (1.f - h0v[h][at]) * acc[h][at];
    }
    __syncwarp();

    #pragma unroll
    for (int at = 0; at < APW; at++) {
        wB[at * PH1 + l]      = t0v[0][at];
        wB[at * PH1 + l + 32] = t0v[1][at];
    }
    __syncwarp();

    // ---- g[f] ----
    {
        float acc[4][APW];
        #pragma unroll
        for (int q = 0; q < 4; q++)
            #pragma unroll
            for (int at = 0; at < APW; at++) acc[q][at] = 0.f;

        for (int j = 0; j < PH1; j += 4) {
            float4 tv[APW];
            #pragma unroll
            for (int at = 0; at < APW; at++)
                tv[at] = *(const float4*)(wB + at * PH1 + j);
            #pragma unroll
            for (int jj = 0; jj < 4; jj++) {
                const float* wrow = sW0 + (j + jj) * W0S + l;
                #pragma unroll
                for (int q = 0; q < 4; q++) {
                    const float wv = wrow[32 * q];
                    #pragma unroll
                    for (int at = 0; at < APW; at++)
                        acc[q][at] += wv * ((const float*)&tv[at])[jj];
                }
            }
        }
        #pragma unroll
        for (int at = 0; at < APW; at++)
            #pragma unroll
            for (int q = 0; q < 4; q++)
                g_grad[(size_t)(a0 + at) * PF + l + 32 * q] = acc[q][at];
    }
}

// ---------------------------------------------------------------------------
// Kernel 2: deterministic Etot reduction (no float atomics)
// ---------------------------------------------------------------------------
__global__ void etot_kernel(float* __restrict__ out)
{
    const int b = blockIdx.x;
    const int tid = threadIdx.x;
    __shared__ float sm[256];
    float s = 0.f;
    for (int i = tid; i < PN; i += 256) s += g_Ei[b * PN + i];
    sm[tid] = s;
    __syncthreads();
    #pragma unroll
    for (int o = 128; o; o >>= 1) {
        if (tid < o) sm[tid] += sm[tid + o];
        __syncthreads();
    }
    if (tid == 0) out[b] = sm[0];
}

// ---------------------------------------------------------------------------
// Kernel 3: force via cp.async double-buffered pipeline.
// dfeat chunks (8 m-rows, 12 KB) stream global->smem via LDGSTS (no register
// round-trip -> low regs, more blocks, deeper async queue). g rows keep the
// register path (needs nv>0 zero-predication). Consume is the proven uniform
// scalar-LDS loop (stride 3, coprime 32 -> conflict-free, zero divergence).
// ---------------------------------------------------------------------------
__global__ void __launch_bounds__(128) force_kernel(
    const float* __restrict__ dfeat,
    const int*   __restrict__ neighbor,
    float*       __restrict__ out)     // out[0..1]=Etot, force at out+2
{
    const int bn  = blockIdx.x;        // 0 .. B*N-1
    const int b   = bn >> 11;          // / PN
    const int tid = threadIdx.x;

    __shared__ float4 buf4[2][768];    // 2 x 12 KB dfeat chunks (8 rows x 384 f)
    __shared__ float4 gs4[2][256];     // 2 x 4 KB g chunks (8 rows x 128 f)
    __shared__ int    sidx[PM];
    __shared__ float  sred[4][3];

    if (tid < PM) sidx[tid] = neighbor[bn * PM + tid];
    __syncthreads();

    const float4* df4 = (const float4*)(dfeat + (size_t)bn * (PM * PF * 3));
    const float4* g4  = (const float4*)(g_grad + (size_t)b * PN * PF);

    float4 rg[2];

    // ---- prologue: chunk 0 ----
    #pragma unroll
    for (int k = 0; k < 6; k++)
        cp_async16(&buf4[0][k * 128 + tid], &df4[k * 128 + tid]);
    CP_COMMIT();
    #pragma unroll
    for (int k = 0; k < 2; k++) {
        const int q = k * 128 + tid;
        const int ml = q >> 5, c2 = q & 31;    // warp-uniform row, lane = col
        const int nv = sidx[ml];
        rg[k] = (nv > 0) ? g4[(size_t)(nv - 1) * 32 + c2]
                         : make_float4(0.f, 0.f, 0.f, 0.f);
    }
    #pragma unroll
    for (int k = 0; k < 2; k++) gs4[0][k * 128 + tid] = rg[k];
    CP_WAIT0();
    __syncthreads();

    float ax = 0.f, ay = 0.f, az = 0.f;

    #pragma unroll
    for (int c = 0; c < 8; c++) {
        const int cur = c & 1;
        if (c < 7) {   // issue async loads for chunk c+1
            #pragma unroll
            for (int k = 0; k < 6; k++)
                cp_async16(&buf4[cur ^ 1][k * 128 + tid],
                           &df4[(c + 1) * 768 + k * 128 + tid]);
            CP_COMMIT();
            #pragma unroll
            for (int k = 0; k < 2; k++) {
                const int q = k * 128 + tid;
                const int ml = q >> 5, c2 = q & 31;
                const int nv = sidx[(c + 1) * 8 + ml];
                rg[k] = (nv > 0) ? g4[(size_t)(nv - 1) * 32 + c2]
                                 : make_float4(0.f, 0.f, 0.f, 0.f);
            }
        }

        // consume chunk c: uniform indexing, no divergence
        const float* bb = (const float*)buf4[cur];
        const float* gg = (const float*)gs4[cur];
        #pragma unroll
        for (int mm = 0; mm < 8; mm++) {
            const float gv = gg[mm * 128 + tid];          // banks tid%32
            const float* row = bb + mm * 384 + tid * 3;   // banks (3*tid)%32
            ax += gv * row[0];
            ay += gv * row[1];
            az += gv * row[2];
        }

        if (c < 7) {
            #pragma unroll
            for (int k = 0; k < 2; k++) gs4[cur ^ 1][k * 128 + tid] = rg[k];
        }
        CP_WAIT0();
        __syncthreads();
    }

    // reduce 128 threads -> 3 floats
    #pragma unroll
    for (int o = 16; o; o >>= 1) {
        ax += __shfl_down_sync(0xffffffffu, ax, o);
        ay += __shfl_down_sync(0xffffffffu, ay, o);
        az += __shfl_down_sync(0xffffffffu, az, o);
    }
    const int w = tid >> 5, l = tid & 31;
    if (l == 0) { sred[w][0] = ax; sred[w][1] = ay; sred[w][2] = az; }
    __syncthreads();
    if (tid < 3) {
        const float v = sred[0][tid] + sred[1][tid] + sred[2][tid] + sred[3][tid];
        out[2 + bn * 3 + tid] = v * 1e10f;
    }
}

// ---------------------------------------------------------------------------
// Launch: single stream (round-10 overlap experiment regressed; reverted).
// ---------------------------------------------------------------------------
extern "C" void kernel_launch(void* const* d_in, const int* in_sizes, int n_in,
                              void* d_out, int out_size)
{
    const float* image    = (const float*)d_in[0];
    const float* dfeat    = (const float*)d_in[1];
    const int*   neighbor = (const int*)  d_in[2];
    // d_in[3] Egroup_weight, d_in[4] divider: unused by the reference math
    const float* W0       = (const float*)d_in[5];
    const float* W1       = (const float*)d_in[6];
    const float* Wout     = (const float*)d_in[7];
    float* out = (float*)d_out;

    const int smem_bytes = (PH1 * W0S + PH2 * W1S + NW * APW * PF
                            + NW * APW * PH1 + PH2) * 4;
    cudaFuncSetAttribute(mlp_kernel, cudaFuncAttributeMaxDynamicSharedMemorySize, smem_bytes);

    mlp_kernel<<<(PB * PN) / APB, NW * 32, smem_bytes>>>(image, W0, W1, Wout);
    etot_kernel<<<PB, 256>>>(out);
    force_kernel<<<PB * PN, 128>>>(dfeat, neighbor, out);
}

// round 13
// speedup vs baseline: 1.1420x; 1.0413x over previous
#include <cuda_runtime.h>

// Problem constants (fixed by the dataset)
#define PB   2      // batch
#define PN   2048   // atoms
#define PM   64     // neighbors
#define PF   128    // features
#define PH1  64
#define PH2  64

#define NW   8      // warps per MLP block
#define APW  2      // atoms per warp
#define APB  (NW * APW)   // atoms per block = 16

// Padded weight row strides (conflict-free banks without index math)
#define W0S  129    // (129*l + f) % 32 == (l+f)%32 -> distinct per lane
#define W1S  65

// Scratch (allocation-free rule: __device__ globals)
__device__ float g_grad[PB * PN * PF];   // dEi/dx per atom, 4 MB (L2-resident)
__device__ float g_Ei[PB * PN];          // per-atom energies

// cp.async helpers (16-byte, cache-global)
__device__ __forceinline__ void cp_async16(void* smem_dst, const void* gmem_src) {
    unsigned s = (unsigned)__cvta_generic_to_shared(smem_dst);
    asm volatile("cp.async.cg.shared.global [%0], [%1], 16;" :: "r"(s), "l"(gmem_src));
}
#define CP_COMMIT() asm volatile("cp.async.commit_group;")
#define CP_WAIT0()  asm volatile("cp.async.wait_group 0;")

// ---------------------------------------------------------------------------
// Kernel 1: warp-private MLP fwd + analytic input-gradient bwd.
// NW=8/APW=2: 2048 warps (14/SM) for latency hiding; padded rows keep both
// row-major (fwd) and column-major (bwd) weight reads conflict-free with
// plain addressing. Staging uses float4 LDG + scalar STS.
// ---------------------------------------------------------------------------
__global__ void __launch_bounds__(NW * 32) mlp_kernel(
    const float* __restrict__ image,
    const float* __restrict__ W0,     // [H1, F]
    const float* __restrict__ W1,     // [H2, H1]
    const float* __restrict__ Wout)   // [1, H2]
{
    extern __shared__ float dyn[];
    float* sW0  = dyn;                     // 64*129 floats, padded rows
    float* sW1  = sW0 + PH1 * W0S;         // 64*65 floats, padded rows
    float* sX   = sW1 + PH2 * W1S;         // NW*APW*PF, plain [at][f]
    float* sBuf = sX + NW * APW * PF;      // NW*APW*PH1, plain [at][j]
    float* sWo  = sBuf + NW * APW * PH1;   // 64

    const int tid = threadIdx.x;
    const int w   = tid >> 5;
    const int l   = tid & 31;

    // ---- stage weights: float4 global reads, scalar padded stores ----
    {
        const float4* w0v = (const float4*)W0;
        for (int i = tid; i < (PH1 * PF) / 4; i += NW * 32) {
            const float4 v = w0v[i];
            const int idx = i * 4;
            float* dst = sW0 + (idx >> 7) * W0S + (idx & 127);
            dst[0] = v.x; dst[1] = v.y; dst[2] = v.z; dst[3] = v.w;
        }
        const float4* w1v = (const float4*)W1;
        for (int i = tid; i < (PH2 * PH1) / 4; i += NW * 32) {
            const float4 v = w1v[i];
            const int idx = i * 4;
            float* dst = sW1 + (idx >> 6) * W1S + (idx & 63);
            dst[0] = v.x; dst[1] = v.y; dst[2] = v.z; dst[3] = v.w;
        }
    }
    if (tid < PH2) sWo[tid] = Wout[tid];
    __syncthreads();

    const int a0 = blockIdx.x * APB + w * APW;
    float* wX = sX + w * (APW * PF);
    float* wB = sBuf + w * (APW * PH1);

    // ---- stage x for APW atoms: contiguous float4, conflict-free ----
    {
        const float4* src = (const float4*)(image + (size_t)a0 * PF);
        float4* dst = (float4*)wX;
        #pragma unroll
        for (int it = 0; it < APW; it++) dst[it * 32 + l] = src[it * 32 + l];
    }
    __syncwarp();

    const float* w0a = sW0 + l * W0S;
    const float* w0b = sW0 + (l + 32) * W0S;
    const float* w1a = sW1 + l * W1S;
    const float* w1b = sW1 + (l + 32) * W1S;

    // ---- L0 forward: h0[j] = sigmoid(sum_f W0[j,f] x[f]), j = l, l+32 ----
    float h0v[2][APW];
    {
        float acc[2][APW];
        #pragma unroll
        for (int h = 0; h < 2; h++)
            #pragma unroll
            for (int at = 0; at < APW; at++) acc[h][at] = 0.f;

        #pragma unroll 4
        for (int f = 0; f < PF; f += 4) {
            float4 xv[APW];
            #pragma unroll
            for (int at = 0; at < APW; at++)
                xv[at] = *(const float4*)(wX + at * PF + f);
            #pragma unroll
            for (int ff = 0; ff < 4; ff++) {
                const float wa = w0a[f + ff];
                const float wb = w0b[f + ff];
                #pragma unroll
                for (int at = 0; at < APW; at++) {
                    const float xe = ((const float*)&xv[at])[ff];
                    acc[0][at] += wa * xe;
                    acc[1][at] += wb * xe;
                }
            }
        }
        #pragma unroll
        for (int h = 0; h < 2; h++)
            #pragma unroll
            for (int at = 0; at < APW; at++)
                h0v[h][at] = 1.f / (1.f + __expf(-acc[h][at]));
    }
    #pragma unroll
    for (int at = 0; at < APW; at++) {
        wB[at * PH1 + l]      = h0v[0][at];
        wB[at * PH1 + l + 32] = h0v[1][at];
    }
    __syncwarp();

    // ---- L1 forward: h1[k] = sigmoid(sum_j W1[k,j] h0[j]), k = l, l+32 ----
    float h1v[2][APW];
    {
        float acc[2][APW];
        #pragma unroll
        for (int h = 0; h < 2; h++)
            #pragma unroll
            for (int at = 0; at < APW; at++) acc[h][at] = 0.f;

        #pragma unroll 4
        for (int j = 0; j < PH1; j += 4) {
            float4 hv[APW];
            #pragma unroll
            for (int at = 0; at < APW; at++)
                hv[at] = *(const float4*)(wB + at * PH1 + j);
            #pragma unroll
            for (int ff = 0; ff < 4; ff++) {
                const float wa = w1a[j + ff];
                const float wb = w1b[j + ff];
                #pragma unroll
                for (int at = 0; at < APW; at++) {
                    const float he = ((const float*)&hv[at])[ff];
                    acc[0][at] += wa * he;
                    acc[1][at] += wb * he;
                }
            }
        }
        #pragma unroll
        for (int h = 0; h < 2; h++)
            #pragma unroll
            for (int at = 0; at < APW; at++)
                h1v[h][at] = 1.f / (1.f + __expf(-acc[h][at]));
    }

    // ---- Ei = sum_k h1[k]*Wout[k] (deterministic warp shuffle reduce) ----
    const float wo0 = sWo[l], wo1 = sWo[l + 32];
    #pragma unroll
    for (int at = 0; at < APW; at++) {
        float v = h1v[0][at] * wo0 + h1v[1][at] * wo1;
        #pragma unroll
        for (int o = 16; o; o >>= 1) v += __shfl_down_sync(0xffffffffu, v, o);
        if (l == 0) g_Ei[a0 + at] = v;
    }
    __syncwarp();

    // ---- t1 = h1*(1-h1)*Wout -> publish (overwrites h0 buffer) ----
    #pragma unroll
    for (int at = 0; at < APW; at++) {
        wB[at * PH1 + l]      = h1v[0][at] * (1.f - h1v[0][at]) * wo0;
        wB[at * PH1 + l + 32] = h1v[1][at] * (1.f - h1v[1][at]) * wo1;
    }
    __syncwarp();

    // ---- gH1[j] = sum_k t1[k]*W1[k,j]; t0 = h0*(1-h0)*gH1, j = l, l+32 ----
    float t0v[2][APW];
    {
        float acc[2][APW];
        #pragma unroll
        for (int h = 0; h < 2; h++)
            #pragma unroll
            for (int at = 0; at < APW; at++) acc[h][at] = 0.f;

        #pragma unroll 4
        for (int k = 0; k < PH2; k += 4) {
            float4 tv[APW];
            #pragma unroll
            for (int at = 0; at < APW; at++)
                tv[at] = *(const float4*)(wB + at * PH1 + k);
            #pragma unroll
            for (int kk = 0; kk < 4; kk++) {
                // column read of padded W1: banks (k*65 + l) % 32 distinct
                const float wa = sW1[(k + kk) * W1S + l];
                const float wb = sW1[(k + kk) * W1S + l + 32];
                #pragma unroll
                for (int at = 0; at < APW; at++) {
                    const float te = ((const float*)&tv[at])[kk];
                    acc[0][at] += wa * te;
                    acc[1][at] += wb * te;
                }
            }
        }
        #pragma unroll
        for (int h = 0; h < 2; h++)
            #pragma unroll
            for (int at = 0; at < APW; at++)
                t0v[h][at] = h0v[h][at] * (1.f - h0v[h][at]) * acc[h][at];
    }
    __syncwarp();

    // ---- publish t0 ----
    #pragma unroll
    for (int at = 0; at < APW; at++) {
        wB[at * PH1 + l]      = t0v[0][at];
        wB[at * PH1 + l + 32] = t0v[1][at];
    }
    __syncwarp();

    // ---- g[f] = sum_j t0[j]*W0[j,f], f = l + 32q ----
    {
        float acc[4][APW];
        #pragma unroll
        for (int q = 0; q < 4; q++)
            #pragma unroll
            for (int at = 0; at < APW; at++) acc[q][at] = 0.f;

        for (int j = 0; j < PH1; j += 4) {
            float4 tv[APW];
            #pragma unroll
            for (int at = 0; at < APW; at++)
                tv[at] = *(const float4*)(wB + at * PH1 + j);
            #pragma unroll
            for (int jj = 0; jj < 4; jj++) {
                const float* wrow = sW0 + (j + jj) * W0S + l;
                #pragma unroll
                for (int q = 0; q < 4; q++) {
                    const float wv = wrow[32 * q];   // banks (j + l) % 32 distinct
                    #pragma unroll
                    for (int at = 0; at < APW; at++)
                        acc[q][at] += wv * ((const float*)&tv[at])[jj];
                }
            }
        }
        #pragma unroll
        for (int at = 0; at < APW; at++)
            #pragma unroll
            for (int q = 0; q < 4; q++)
                g_grad[(size_t)(a0 + at) * PF + l + 32 * q] = acc[q][at];
    }
}

// ---------------------------------------------------------------------------
// Kernel 2: deterministic Etot reduction (no float atomics)
// ---------------------------------------------------------------------------
__global__ void etot_kernel(float* __restrict__ out)
{
    const int b = blockIdx.x;
    const int tid = threadIdx.x;
    __shared__ float sm[256];
    float s = 0.f;
    for (int i = tid; i < PN; i += 256) s += g_Ei[b * PN + i];
    sm[tid] = s;
    __syncthreads();
    #pragma unroll
    for (int o = 128; o; o >>= 1) {
        if (tid < o) sm[tid] += sm[tid + o];
        __syncthreads();
    }
    if (tid == 0) out[b] = sm[0];
}

// ---------------------------------------------------------------------------
// Kernel 3: force via cp.async double-buffered pipeline. (round-11 WIN, unchanged)
// ---------------------------------------------------------------------------
__global__ void __launch_bounds__(128) force_kernel(
    const float* __restrict__ dfeat,
    const int*   __restrict__ neighbor,
    float*       __restrict__ out)     // out[0..1]=Etot, force at out+2
{
    const int bn  = blockIdx.x;        // 0 .. B*N-1
    const int b   = bn >> 11;          // / PN
    const int tid = threadIdx.x;

    __shared__ float4 buf4[2][768];    // 2 x 12 KB dfeat chunks (8 rows x 384 f)
    __shared__ float4 gs4[2][256];     // 2 x 4 KB g chunks (8 rows x 128 f)
    __shared__ int    sidx[PM];
    __shared__ float  sred[4][3];

    if (tid < PM) sidx[tid] = neighbor[bn * PM + tid];
    __syncthreads();

    const float4* df4 = (const float4*)(dfeat + (size_t)bn * (PM * PF * 3));
    const float4* g4  = (const float4*)(g_grad + (size_t)b * PN * PF);

    float4 rg[2];

    // ---- prologue: chunk 0 ----
    #pragma unroll
    for (int k = 0; k < 6; k++)
        cp_async16(&buf4[0][k * 128 + tid], &df4[k * 128 + tid]);
    CP_COMMIT();
    #pragma unroll
    for (int k = 0; k < 2; k++) {
        const int q = k * 128 + tid;
        const int ml = q >> 5, c2 = q & 31;    // warp-uniform row, lane = col
        const int nv = sidx[ml];
        rg[k] = (nv > 0) ? g4[(size_t)(nv - 1) * 32 + c2]
                         : make_float4(0.f, 0.f, 0.f, 0.f);
    }
    #pragma unroll
    for (int k = 0; k < 2; k++) gs4[0][k * 128 + tid] = rg[k];
    CP_WAIT0();
    __syncthreads();

    float ax = 0.f, ay = 0.f, az = 0.f;

    #pragma unroll
    for (int c = 0; c < 8; c++) {
        const int cur = c & 1;
        if (c < 7) {   // issue async loads for chunk c+1
            #pragma unroll
            for (int k = 0; k < 6; k++)
                cp_async16(&buf4[cur ^ 1][k * 128 + tid],
                           &df4[(c + 1) * 768 + k * 128 + tid]);
            CP_COMMIT();
            #pragma unroll
            for (int k = 0; k < 2; k++) {
                const int q = k * 128 + tid;
                const int ml = q >> 5, c2 = q & 31;
                const int nv = sidx[(c + 1) * 8 + ml];
                rg[k] = (nv > 0) ? g4[(size_t)(nv - 1) * 32 + c2]
                                 : make_float4(0.f, 0.f, 0.f, 0.f);
            }
        }

        // consume chunk c: uniform indexing, no divergence
        const float* bb = (const float*)buf4[cur];
        const float* gg = (const float*)gs4[cur];
        #pragma unroll
        for (int mm = 0; mm < 8; mm++) {
            const float gv = gg[mm * 128 + tid];          // banks tid%32
            const float* row = bb + mm * 384 + tid * 3;   // banks (3*tid)%32
            ax += gv * row[0];
            ay += gv * row[1];
            az += gv * row[2];
        }

        if (c < 7) {
            #pragma unroll
            for (int k = 0; k < 2; k++) gs4[cur ^ 1][k * 128 + tid] = rg[k];
        }
        CP_WAIT0();
        __syncthreads();
    }

    // reduce 128 threads -> 3 floats
    #pragma unroll
    for (int o = 16; o; o >>= 1) {
        ax += __shfl_down_sync(0xffffffffu, ax, o);
        ay += __shfl_down_sync(0xffffffffu, ay, o);
        az += __shfl_down_sync(0xffffffffu, az, o);
    }
    const int w = tid >> 5, l = tid & 31;
    if (l == 0) { sred[w][0] = ax; sred[w][1] = ay; sred[w][2] = az; }
    __syncthreads();
    if (tid < 3) {
        const float v = sred[0][tid] + sred[1][tid] + sred[2][tid] + sred[3][tid];
        out[2 + bn * 3 + tid] = v * 1e10f;
    }
}

// ---------------------------------------------------------------------------
extern "C" void kernel_launch(void* const* d_in, const int* in_sizes, int n_in,
                              void* d_out, int out_size)
{
    const float* image    = (const float*)d_in[0];
    const float* dfeat    = (const float*)d_in[1];
    const int*   neighbor = (const int*)  d_in[2];
    // d_in[3] Egroup_weight, d_in[4] divider: unused by the reference math
    const float* W0       = (const float*)d_in[5];
    const float* W1       = (const float*)d_in[6];
    const float* Wout     = (const float*)d_in[7];
    float* out = (float*)d_out;

    const int smem_bytes = (PH1 * W0S + PH2 * W1S + NW * APW * PF
                            + NW * APW * PH1 + PH2) * 4;
    cudaFuncSetAttribute(mlp_kernel, cudaFuncAttributeMaxDynamicSharedMemorySize, smem_bytes);

    mlp_kernel<<<(PB * PN) / APB, NW * 32, smem_bytes>>>(image, W0, W1, Wout);
    etot_kernel<<<PB, 256>>>(out);
    force_kernel<<<PB * PN, 128>>>(dfeat, neighbor, out);
}